// round 1
// baseline (speedup 1.0000x reference)
#include <cuda_runtime.h>
#include <cstdint>

// ---------------------------------------------------------------------------
// FeatureLevel: fake-quant (4-bit levels) of two feature grids + gather.
//   g0: [1,8,2048,2048]  -> 4-corner raw gather (32 feats)
//   g1: [1,8,1024,1024]  -> bilinear grid_sample, zeros padding (8 feats)
//   out: [N, 40] float32, N = 2097152
//
// Strategy: prepass quantizes grids to uint8 codes AND transposes to
// [H,W,C]-packed u64 (8 channels = 8 bytes per texel). Code tables total
// ~42MB -> L2 resident. Gather kernel then does 8 single-sector u64 loads
// per point and exact dequant (code * 1/16 - 15/32).
// ---------------------------------------------------------------------------

#define R0 2048
#define R1 1024
#define CCH 8

// Scratch (no cudaMalloc allowed): packed code tables.
__device__ unsigned long long g_codes0[(size_t)R0 * R0];   // 33.5 MB
__device__ unsigned long long g_codes1[(size_t)R1 * R1];   //  8.4 MB

__device__ __forceinline__ float dq(unsigned c) {
    // exact: c/16 - 15/32, both representable, result multiple of 1/32
    return fmaf((float)c, 0.0625f, -0.46875f);
}

__device__ __forceinline__ unsigned qcode(float x) {
    // codes = clip(round((x - lo)/q), 0, 15); lo = -0.46875, 1/q = 16 (exact)
    float c = rintf(__fmul_rn(__fadd_rn(x, 0.46875f), 16.0f));
    c = fminf(fmaxf(c, 0.0f), 15.0f);
    return (unsigned)c;
}

// Quantize + transpose [C,H,W] float -> [H*W] u64 (8 packed uint8 codes).
template <int RES>
__global__ __launch_bounds__(256) void quant_pack_kernel(
    const float* __restrict__ g, unsigned long long* __restrict__ codes) {
    int idx = blockIdx.x * blockDim.x + threadIdx.x;
    if (idx >= RES * RES) return;
    const size_t plane = (size_t)RES * RES;
    unsigned long long packed = 0;
#pragma unroll
    for (int c = 0; c < CCH; c++) {
        float x = __ldg(g + (size_t)c * plane + idx);
        packed |= ((unsigned long long)qcode(x)) << (8 * c);
    }
    codes[idx] = packed;
}

__global__ __launch_bounds__(256) void gather_kernel(
    const float2* __restrict__ uv, float* __restrict__ out, int n) {
    int i = blockIdx.x * blockDim.x + threadIdx.x;
    if (i >= n) return;

    float2 p = uv[i];
    float o[40];

    // ---------------- G0: 4-neighbor raw gather ----------------
    // pos = uv*2048 - 0.5 (uv*2048 exact -> fma-safe)
    float px = __fadd_rn(__fmul_rn(p.x, (float)R0), -0.5f);
    float py = __fadd_rn(__fmul_rn(p.y, (float)R0), -0.5f);
    int x0 = (int)fminf(fmaxf(floorf(px), 0.0f), (float)(R0 - 2));
    int y0 = (int)fminf(fmaxf(floorf(py), 0.0f), (float)(R0 - 2));

    size_t r0 = (size_t)y0 * R0 + x0;
    size_t r1 = r0 + R0;
    unsigned long long v00 = g_codes0[r0];
    unsigned long long v01 = g_codes0[r0 + 1];
    unsigned long long v10 = g_codes0[r1];
    unsigned long long v11 = g_codes0[r1 + 1];
#pragma unroll
    for (int c = 0; c < CCH; c++) {
        o[c]      = dq((unsigned)(v00 >> (8 * c)) & 0xFFu);
        o[8 + c]  = dq((unsigned)(v01 >> (8 * c)) & 0xFFu);
        o[16 + c] = dq((unsigned)(v10 >> (8 * c)) & 0xFFu);
        o[24 + c] = dq((unsigned)(v11 >> (8 * c)) & 0xFFu);
    }

    // ---------------- G1: bilinear grid_sample (zeros pad) ----------------
    // Replicate reference op order exactly (no FMA contraction) so floor()
    // boundaries match bit-for-bit.
    float gx = __fadd_rn(__fmul_rn(p.x, 2.0f), -1.0f);
    float gy = __fadd_rn(__fmul_rn(p.y, 2.0f), -1.0f);
    float ix = __fadd_rn(__fmul_rn(__fmul_rn(__fadd_rn(gx, 1.0f), 0.5f), (float)R1), -0.5f);
    float iy = __fadd_rn(__fmul_rn(__fmul_rn(__fadd_rn(gy, 1.0f), 0.5f), (float)R1), -0.5f);

    float fx0 = floorf(ix), fy0 = floorf(iy);
    float wx1 = __fadd_rn(ix, -fx0);
    float wy1 = __fadd_rn(iy, -fy0);
    float wx0 = __fadd_rn(1.0f, -wx1);
    float wy0 = __fadd_rn(1.0f, -wy1);

    int jx0 = (int)fx0, jy0 = (int)fy0;
    int jx1 = jx0 + 1, jy1 = jy0 + 1;
    bool vx0 = (jx0 >= 0) & (jx0 <= R1 - 1);
    bool vx1 = (jx1 >= 0) & (jx1 <= R1 - 1);
    bool vy0 = (jy0 >= 0) & (jy0 <= R1 - 1);
    bool vy1 = (jy1 >= 0) & (jy1 <= R1 - 1);

    float w00 = __fmul_rn(wx0, wy0);
    float w10 = __fmul_rn(wx1, wy0);
    float w01 = __fmul_rn(wx0, wy1);
    float w11 = __fmul_rn(wx1, wy1);

    float acc[CCH];
#pragma unroll
    for (int c = 0; c < CCH; c++) acc[c] = 0.0f;

    // reference sum order: t(x0,y0) + t(x1,y0) + t(x0,y1) + t(x1,y1)
    if (vy0) {
        size_t row = (size_t)jy0 * R1;
        if (vx0) {
            unsigned long long t = g_codes1[row + jx0];
#pragma unroll
            for (int c = 0; c < CCH; c++)
                acc[c] = fmaf(dq((unsigned)(t >> (8 * c)) & 0xFFu), w00, acc[c]);
        }
        if (vx1) {
            unsigned long long t = g_codes1[row + jx1];
#pragma unroll
            for (int c = 0; c < CCH; c++)
                acc[c] = fmaf(dq((unsigned)(t >> (8 * c)) & 0xFFu), w10, acc[c]);
        }
    }
    if (vy1) {
        size_t row = (size_t)jy1 * R1;
        if (vx0) {
            unsigned long long t = g_codes1[row + jx0];
#pragma unroll
            for (int c = 0; c < CCH; c++)
                acc[c] = fmaf(dq((unsigned)(t >> (8 * c)) & 0xFFu), w01, acc[c]);
        }
        if (vx1) {
            unsigned long long t = g_codes1[row + jx1];
#pragma unroll
            for (int c = 0; c < CCH; c++)
                acc[c] = fmaf(dq((unsigned)(t >> (8 * c)) & 0xFFu), w11, acc[c]);
        }
    }
#pragma unroll
    for (int c = 0; c < CCH; c++) o[32 + c] = acc[c];

    // ---------------- store [N,40], 160B/row, 16B aligned ----------------
    float4* dst = (float4*)(out + (size_t)i * 40);
#pragma unroll
    for (int j = 0; j < 10; j++) {
        dst[j] = make_float4(o[4 * j], o[4 * j + 1], o[4 * j + 2], o[4 * j + 3]);
    }
}

extern "C" void kernel_launch(void* const* d_in, const int* in_sizes, int n_in,
                              void* d_out, int out_size) {
    const float* uv = (const float*)d_in[0];
    const float* g0 = (const float*)d_in[1];
    const float* g1 = (const float*)d_in[2];
    float* out = (float*)d_out;

    int n = in_sizes[0] / 2;

    unsigned long long* c0;
    unsigned long long* c1;
    cudaGetSymbolAddress((void**)&c0, g_codes0);
    cudaGetSymbolAddress((void**)&c1, g_codes1);

    // Prepass: fake-quant + transpose-pack both grids.
    quant_pack_kernel<R0><<<(R0 * R0 + 255) / 256, 256>>>(g0, c0);
    quant_pack_kernel<R1><<<(R1 * R1 + 255) / 256, 256>>>(g1, c1);

    // Main gather.
    gather_kernel<<<(n + 255) / 256, 256>>>((const float2*)uv, out, n);
}